// round 14
// baseline (speedup 1.0000x reference)
#include <cuda_runtime.h>
#include <cstdint>

#define B   32
#define H   384
#define W   640
#define C   128
#define HS  96      // H / SCALE
#define WS  160     // W / SCALE
#define FW  30
#define THRESH 0.015f
#define TOPK 2000
#define GRIDF 768      // fused kernel grid: co-resident (<= 152 SMs * 6 blocks @ 42 regs)
#define NTH  256
#define PIXS 16        // pixels per thread in select swath (256*16 = 4096 px)

// Static device scratch (allocation-free rule: __device__ globals allowed)
__device__ float d_hwc[(size_t)B * HS * WS * C];   // transposed featmap (needed rows only)
__device__ int   d_idx[B * TOPK];                  // ascending selected linear indices, -1 invalid
__device__ int   d_ymin[B];                        // first needed feat row per batch
__device__ int   d_nrows[B];                       // number of needed feat rows per batch
__device__ int      g_barCount;                    // self-resetting arrival counter
__device__ unsigned g_barSense;                    // monotonically increasing sense

// ---------------------------------------------------------------------------
// Replay-safe sense-reversing grid barrier (proven in R8). Count self-resets;
// sense only increments. Requires all GRIDF blocks co-resident.
// ---------------------------------------------------------------------------
__device__ __forceinline__ void grid_barrier()
{
    __threadfence();
    __syncthreads();
    if (threadIdx.x == 0) {
        unsigned s0 = atomicAdd(&g_barSense, 0u);
        int my = atomicAdd(&g_barCount, 1);
        if (my == GRIDF - 1) {
            g_barCount = 0;
            __threadfence();
            atomicAdd(&g_barSense, 1u);
        } else {
            while (atomicAdd(&g_barSense, 0u) == s0) { __nanosleep(64); }
        }
        __threadfence();
    }
    __syncthreads();
}

// ---------------------------------------------------------------------------
// Fused kernel: blocks 0..31 do ordered selection (one batch each); then a
// grid barrier; then ALL 768 blocks run the sparse CHW->HWC transpose over
// the compact task list. 256 threads per block.
// ---------------------------------------------------------------------------
__global__ __launch_bounds__(NTH, 6) void fused_kernel(
    const float* __restrict__ prob,
    const float* __restrict__ feat,
    const float* __restrict__ ratio,
    const int* __restrict__ rshape_raw,
    float* __restrict__ pts_out)
{
    __shared__ float tile[32][33];        // transpose tile (select doesn't use it)
    __shared__ int sW[8];                 // warp scan scratch
    __shared__ int sBase, sTotal;
    __shared__ int sRmin, sRmax;
    __shared__ int sOffT[B + 1];
    __shared__ int sYminT[B];

    const int tid  = threadIdx.x;
    const int warp = tid >> 5;
    const int lane = tid & 31;

    // ======================= Phase A: ordered selection =======================
    if (blockIdx.x < B) {
        const int b = blockIdx.x;
        if (tid == 0) { sBase = 0; sRmin = 0x7fffffff; sRmax = -1; }

        // r_shape dtype sniff: int64 LE -> word 1 is high half of first value
        // (0, since H fits in 32 bits); int32 -> word 1 is W != 0.
        const int stride = (rshape_raw[1] == 0) ? 2 : 1;
        const int r0 = rshape_raw[(2 * b)     * stride];
        const int r1 = rshape_raw[(2 * b + 1) * stride];
        const int rowW     = r1 - 2 * FW;              // valid cols per row
        const int totalPix = (r0 - 2 * FW) * rowW;     // in-region pixel count
        const float rv = ratio[b];
        const float* pb = prob + (size_t)b * H * W;

        __syncthreads();

        for (int sw = 0; sw < totalPix; sw += NTH * PIXS) {
            const int pix0 = sw + PIXS * tid;
            unsigned pmask = 0;
            int ri0 = 0, ci0 = 0;
            if (rowW > 0 && pix0 < totalPix) {
                const int rq = pix0 / rowW;
                ri0 = FW + rq;
                ci0 = FW + pix0 - rq * rowW;
                int ri = ri0, ci = ci0;
                #pragma unroll
                for (int j = 0; j < PIXS; ++j) {
                    if ((pix0 + j) < totalPix && pb[(size_t)ri * W + ci] > THRESH)
                        pmask |= (1u << j);
                    if (++ci >= FW + rowW) { ci = FW; ++ri; }
                }
            }
            const int cnt = __popc(pmask);

            // warp scan + serial 8-warp prefix
            int incl = cnt;
            #pragma unroll
            for (int d = 1; d < 32; d <<= 1) {
                int y = __shfl_up_sync(0xffffffffu, incl, d);
                if (lane >= d) incl += y;
            }
            if (lane == 31) sW[warp] = incl;
            __syncthreads();
            if (tid == 0) {
                int acc = 0;
                #pragma unroll
                for (int w = 0; w < 8; ++w) { int v = sW[w]; sW[w] = acc; acc += v; }
                sTotal = acc;
            }
            __syncthreads();
            int pos = sBase + sW[warp] + (incl - cnt);

            if (pmask) {
                int myRmin = 0x7fffffff, myRmax = -1;
                int ri = ri0, ci = ci0;
                #pragma unroll
                for (int j = 0; j < PIXS; ++j) {
                    if ((pmask >> j) & 1u) {
                        if (pos < TOPK) {
                            d_idx[b * TOPK + pos] = ri * W + ci;
                            ((float2*)pts_out)[(size_t)b * TOPK + pos] =
                                make_float2((float)ci / rv, (float)ri / rv);
                            if (ri < myRmin) myRmin = ri;
                            if (ri > myRmax) myRmax = ri;
                        }
                        ++pos;
                    }
                    if (++ci >= FW + rowW) { ci = FW; ++ri; }
                }
                if (myRmax >= 0) {
                    atomicMin(&sRmin, myRmin);
                    atomicMax(&sRmax, myRmax);
                }
            }
            __syncthreads();
            if (tid == 0) sBase += sTotal;
            __syncthreads();
            if (sBase >= TOPK) break;
        }

        __syncthreads();
        const int base = (sBase < TOPK) ? sBase : TOPK;
        for (int k = base + tid; k < TOPK; k += NTH) {
            d_idx[b * TOPK + k] = -1;
            ((float2*)pts_out)[(size_t)b * TOPK + k] = make_float2(0.0f, 0.0f);
        }
        if (tid == 0) {
            if (sRmax < 0) {
                d_ymin[b] = 0; d_nrows[b] = 0;
            } else {
                int ymin = sRmin >> 2;
                int ymax = (sRmax >> 2) + 1;
                if (ymax > HS - 1) ymax = HS - 1;
                d_ymin[b] = ymin;
                d_nrows[b] = ymax - ymin + 1;
            }
        }
    }

    grid_barrier();

    // =================== Phase B: sparse CHW -> HWC transpose ===================
    {
        if (tid == 0) {
            int acc = 0;
            #pragma unroll
            for (int b2 = 0; b2 < B; ++b2) {
                sOffT[b2] = acc;
                sYminT[b2] = d_ymin[b2];
                acc += d_nrows[b2];
            }
            sOffT[B] = acc;
        }
        __syncthreads();
        const int totalTasks = sOffT[B] * 20;

        const int tx = tid & 31;   // 0..31
        const int ty = tid >> 5;   // 0..7

        for (int t = blockIdx.x; t < totalTasks; t += GRIDF) {
            const int rowTask = t / 20;
            const int tileId  = t - rowTask * 20;
            int b2 = 0;
            while (sOffT[b2 + 1] <= rowTask) ++b2;     // uniform across block
            const int y  = sYminT[b2] + (rowTask - sOffT[b2]);
            const int xt = tileId % 5;                 // x tile of 32
            const int ct = tileId / 5;                 // c tile of 32

            const float* src = feat + ((size_t)b2 * C) * (HS * WS) + (size_t)y * WS;
            #pragma unroll
            for (int i = 0; i < 4; ++i) {
                const int cc = ct * 32 + ty + i * 8;
                tile[ty + i * 8][tx] = src[(size_t)cc * (HS * WS) + xt * 32 + tx];
            }
            __syncthreads();
            float* dst = d_hwc + ((size_t)(b2 * HS + y) * WS) * C;
            #pragma unroll
            for (int i = 0; i < 4; ++i) {
                const int x = xt * 32 + ty + i * 8;
                dst[(size_t)x * C + ct * 32 + tx] = tile[tx][ty + i * 8];
            }
            __syncthreads();
        }
    }
}

// ---------------------------------------------------------------------------
// Gather: exact cover, 80 points/block (25 x B blocks, 25*80 = TOPK exactly).
// 256 threads = 8 warps x 32 channel-lanes; warp wp owns points wp*10..+9,
// all 10 iterations independent (no dedup state) so tap LDG.128s batch for
// high MLP. Decode once into smem.
// ---------------------------------------------------------------------------
__global__ __launch_bounds__(256) void gather_kernel(float* __restrict__ des_out)
{
    const int b   = blockIdx.y;
    const int p0  = blockIdx.x * 80;
    const int tid = threadIdx.x;
    const int cg  = tid & 31;
    const int wp  = tid >> 5;

    __shared__ int    sOff[80];
    __shared__ float4 sWt[80];
    if (tid < 80) {
        const int p = p0 + tid;                 // always < TOPK (exact cover)
        const int lin = d_idx[b * TOPK + p];
        int off = -1;
        float4 wt = make_float4(0.f, 0.f, 0.f, 0.f);
        if (lin >= 0) {
            const int y = lin / W;
            const int x = lin - y * W;
            const int x0 = x >> 2;
            const int y0 = y >> 2;
            const float fx = (float)(x & 3) * 0.25f;
            const float fy = (float)(y & 3) * 0.25f;
            off = ((b * HS + y0) * WS + x0) * 32;   // float4 units
            wt = make_float4((1.f - fx) * (1.f - fy),   // Ia (y0,x0)
                             (1.f - fx) * fy,           // Ib (y1,x0)
                             fx * (1.f - fy),           // Ic (y0,x1)
                             fx * fy);                  // Id (y1,x1)
        }
        sOff[tid] = off;
        sWt[tid]  = wt;
    }
    __syncthreads();

    const float4* hwc4 = (const float4*)d_hwc;
    float4* out4 = (float4*)des_out;
    const int jb = wp * 10;

    #pragma unroll
    for (int k = 0; k < 10; ++k) {
        const int j = jb + k;
        const int p = p0 + j;
        const int off = sOff[j];
        float4 v = make_float4(0.f, 0.f, 0.f, 0.f);
        if (off >= 0) {
            const float4 w = sWt[j];
            const float4* basep = hwc4 + off + cg;
            const float4 Ia = basep[0];
            const float4 Ic = basep[32];
            const float4 Ib = basep[WS * 32];
            const float4 Id = basep[WS * 32 + 32];
            v.x = Ia.x * w.x + Ib.x * w.y + Ic.x * w.z + Id.x * w.w;
            v.y = Ia.y * w.x + Ib.y * w.y + Ic.y * w.z + Id.y * w.w;
            v.z = Ia.z * w.x + Ib.z * w.y + Ic.z * w.z + Id.z * w.w;
            v.w = Ia.w * w.x + Ib.w * w.y + Ic.w * w.z + Id.w * w.w;
        }
        out4[((size_t)b * TOPK + p) * 32 + cg] = v;
    }
}

// ---------------------------------------------------------------------------
extern "C" void kernel_launch(void* const* d_in, const int* in_sizes, int n_in,
                              void* d_out, int out_size)
{
    const float* prob   = (const float*)d_in[0];      // [B,1,H,W]
    const float* feat   = (const float*)d_in[1];      // [B,C,HS,WS]
    const float* ratio  = (const float*)d_in[2];      // [B,1]
    const int*   rshape = (const int*)d_in[3];        // [B,2] int32 (or int64-packed)

    float* pts_out = (float*)d_out;                        // [B,TOPK,2]
    float* des_out = (float*)d_out + (size_t)B * TOPK * 2; // [B,TOPK,C]

    fused_kernel<<<GRIDF, NTH>>>(prob, feat, ratio, rshape, pts_out);
    gather_kernel<<<dim3(TOPK / 80, B), 256>>>(des_out);
}

// round 17
// speedup vs baseline: 1.0830x; 1.0830x over previous
#include <cuda_runtime.h>
#include <cstdint>

#define B   32
#define H   384
#define W   640
#define C   128
#define HS  96      // H / SCALE
#define WS  160     // W / SCALE
#define FW  30
#define THRESH 0.015f
#define TOPK 2000
#define TBLOCKS 2048   // persistent transpose grid
#define PIX 4          // pixels per thread per swath in select

// Static device scratch (allocation-free rule: __device__ globals allowed)
__device__ float d_hwc[(size_t)B * HS * WS * C];   // transposed featmap (only needed rows valid)
__device__ int   d_idx[B * TOPK];                  // selected linear pixel indices, -1 = invalid
__device__ int   d_ymin[B];                        // first needed feat row per batch
__device__ int   d_nrows[B];                       // number of needed feat rows per batch

// ---------------------------------------------------------------------------
// Kernel 1: ordered selection, swath-parallel (proven R4/R9). One block per
// batch; swaths of 1024*PIX pixels; one block scan per swath; early exit.
// ---------------------------------------------------------------------------
__global__ __launch_bounds__(1024) void select_kernel(
    const float* __restrict__ prob,
    const float* __restrict__ ratio,
    const int* __restrict__ rshape_raw,
    float* __restrict__ pts_out)
{
    const int b    = blockIdx.x;
    const int tid  = threadIdx.x;
    const int warp = tid >> 5;
    const int lane = tid & 31;

    __shared__ int sWarpBase[32];
    __shared__ int sTotal;
    __shared__ int sBase;
    __shared__ int sRmin, sRmax;
    if (tid == 0) { sBase = 0; sRmin = 0x7fffffff; sRmax = -1; }

    // r_shape dtype sniff: int64 LE -> word 1 is high half of first value (0);
    // int32 -> word 1 is W != 0.
    const int stride = (rshape_raw[1] == 0) ? 2 : 1;
    const int r0 = rshape_raw[(2 * b)     * stride];
    const int r1 = rshape_raw[(2 * b + 1) * stride];
    const int rowW     = r1 - 2 * FW;              // valid cols per row
    const int totalPix = (r0 - 2 * FW) * rowW;     // in-region pixel count
    const float rv = ratio[b];
    const float* pb = prob + (size_t)b * H * W;

    __syncthreads();

    for (int sw = 0; sw < totalPix; sw += 1024 * PIX) {
        const int pix0 = sw + PIX * tid;
        unsigned pmask = 0;
        int rr[PIX], cc[PIX];
        if (rowW > 0 && pix0 < totalPix) {
            const int rq = pix0 / rowW;
            int ri = FW + rq, ci = FW + pix0 - rq * rowW;
            #pragma unroll
            for (int j = 0; j < PIX; ++j) {
                rr[j] = ri; cc[j] = ci;
                if ((pix0 + j) < totalPix && pb[(size_t)ri * W + ci] > THRESH)
                    pmask |= (1u << j);
                if (++ci >= FW + rowW) { ci = FW; ++ri; }
            }
        }
        const int cnt = __popc(pmask);

        int incl = cnt;
        #pragma unroll
        for (int d = 1; d < 32; d <<= 1) {
            int y = __shfl_up_sync(0xffffffffu, incl, d);
            if (lane >= d) incl += y;
        }
        if (lane == 31) sWarpBase[warp] = incl;
        __syncthreads();
        if (tid < 32) {
            int v = sWarpBase[tid];
            int x = v;
            #pragma unroll
            for (int d = 1; d < 32; d <<= 1) {
                int y = __shfl_up_sync(0xffffffffu, x, d);
                if (tid >= d) x += y;
            }
            sWarpBase[tid] = x - v;
            if (tid == 31) sTotal = x;
        }
        __syncthreads();
        int pos = sBase + sWarpBase[warp] + (incl - cnt);

        int myRmin = 0x7fffffff, myRmax = -1;
        #pragma unroll
        for (int j = 0; j < PIX; ++j) {
            if (pmask & (1u << j)) {
                if (pos < TOPK) {
                    d_idx[b * TOPK + pos] = rr[j] * W + cc[j];
                    ((float2*)pts_out)[(size_t)b * TOPK + pos] =
                        make_float2((float)cc[j] / rv, (float)rr[j] / rv);
                    if (rr[j] < myRmin) myRmin = rr[j];
                    if (rr[j] > myRmax) myRmax = rr[j];
                }
                ++pos;
            }
        }
        if (myRmax >= 0) {
            atomicMin(&sRmin, myRmin);
            atomicMax(&sRmax, myRmax);
        }
        __syncthreads();
        if (tid == 0) sBase += sTotal;
        __syncthreads();
        if (sBase >= TOPK) break;
    }

    __syncthreads();
    {
        const int base = (sBase < TOPK) ? sBase : TOPK;
        for (int k = base + tid; k < TOPK; k += 1024) {
            d_idx[b * TOPK + k] = -1;
            ((float2*)pts_out)[(size_t)b * TOPK + k] = make_float2(0.0f, 0.0f);
        }
        if (tid == 0) {
            if (sRmax < 0) {
                d_ymin[b] = 0; d_nrows[b] = 0;
            } else {
                int ymin = sRmin >> 2;
                int ymax = (sRmax >> 2) + 1;
                if (ymax > HS - 1) ymax = HS - 1;
                d_ymin[b] = ymin;
                d_nrows[b] = ymax - ymin + 1;
            }
        }
    }
}

// ---------------------------------------------------------------------------
// Kernel 2: persistent CHW -> HWC transpose over a compact task list
// (proven). Task = (batch, feat row, tile); 20 tiles per row.
// ---------------------------------------------------------------------------
__global__ __launch_bounds__(256) void transpose_kernel(const float* __restrict__ feat)
{
    __shared__ int sOff[B + 1];
    __shared__ int sYmin[B];
    __shared__ float tile[32][33];

    const int t0 = threadIdx.y * 32 + threadIdx.x;
    if (t0 == 0) {
        int acc = 0;
        #pragma unroll
        for (int b = 0; b < B; ++b) {
            sOff[b] = acc;
            sYmin[b] = d_ymin[b];
            acc += d_nrows[b];
        }
        sOff[B] = acc;
    }
    __syncthreads();
    const int totalTasks = sOff[B] * 20;

    const int tx = threadIdx.x;  // 0..31
    const int ty = threadIdx.y;  // 0..7

    for (int t = blockIdx.x; t < totalTasks; t += TBLOCKS) {
        const int rowTask = t / 20;
        const int tileId  = t - rowTask * 20;
        int b = 0;
        while (sOff[b + 1] <= rowTask) ++b;        // uniform across block
        const int y  = sYmin[b] + (rowTask - sOff[b]);
        const int xt = tileId % 5;                 // 0..4 (x tiles of 32)
        const int ct = tileId / 5;                 // 0..3 (c tiles of 32)

        const float* src = feat + ((size_t)b * C) * (HS * WS) + (size_t)y * WS;
        #pragma unroll
        for (int i = 0; i < 4; ++i) {
            const int cc = ct * 32 + ty + i * 8;
            tile[ty + i * 8][tx] = src[(size_t)cc * (HS * WS) + xt * 32 + tx];
        }
        __syncthreads();
        float* dst = d_hwc + ((size_t)(b * HS + y) * WS) * C;
        #pragma unroll
        for (int i = 0; i < 4; ++i) {
            const int x = xt * 32 + ty + i * 8;
            dst[(size_t)x * C + ct * 32 + tx] = tile[tx][ty + i * 8];
        }
        __syncthreads();
    }
}

// ---------------------------------------------------------------------------
// Kernel 3: dual-point software-pipelined bilinear gather.
// Exact cover: 80 points/block, grid (25, B). 256 threads = 8 warps x 32
// channel-lanes; warp wp owns points jb..jb+9. Each iteration processes TWO
// independent points (j, j+5): 8 tap LDG.128s in flight per thread (2x the
// MLP of the single-point loop that ptxas serialized at regs=32).
// ---------------------------------------------------------------------------
__global__ void gather_kernel(float* __restrict__ des_out)
{
    const int b   = blockIdx.y;
    const int p0  = blockIdx.x * 80;
    const int tid = threadIdx.x;
    const int cg  = tid & 31;   // channel group (float4 lane)
    const int wp  = tid >> 5;   // warp 0..7

    __shared__ int    sOff[80];
    __shared__ float4 sWt[80];
    if (tid < 80) {
        const int p = p0 + tid;                 // always < TOPK (exact cover)
        const int lin = d_idx[b * TOPK + p];
        int off = -1;
        float4 wt = make_float4(0.f, 0.f, 0.f, 0.f);
        if (lin >= 0) {
            const int y = lin / W;
            const int x = lin - y * W;
            const int x0 = x >> 2;
            const int y0 = y >> 2;
            const float fx = (float)(x & 3) * 0.25f;
            const float fy = (float)(y & 3) * 0.25f;
            off = ((b * HS + y0) * WS + x0) * 32;   // float4 units
            wt = make_float4((1.f - fx) * (1.f - fy),   // Ia (y0,x0)
                             (1.f - fx) * fy,           // Ib (y1,x0)
                             fx * (1.f - fy),           // Ic (y0,x1)
                             fx * fy);                  // Id (y1,x1)
        }
        sOff[tid] = off;
        sWt[tid]  = wt;
    }
    __syncthreads();

    const float4* hwc4 = (const float4*)d_hwc;
    float4* out4 = (float4*)des_out;
    const int jb = wp * 10;
    const float4 Z = make_float4(0.f, 0.f, 0.f, 0.f);

    #pragma unroll
    for (int k = 0; k < 5; ++k) {
        const int jA = jb + k;          // first point of the pair
        const int jB = jb + 5 + k;      // second (independent) point
        const int offA = sOff[jA];
        const int offB = sOff[jB];

        // issue all 8 tap loads before any compute
        float4 Aa = Z, Ab = Z, Ac = Z, Ad = Z;
        float4 Ba = Z, Bb = Z, Bc = Z, Bd = Z;
        if (offA >= 0) {
            const float4* pA = hwc4 + offA + cg;
            Aa = pA[0];
            Ac = pA[32];
            Ab = pA[WS * 32];
            Ad = pA[WS * 32 + 32];
        }
        if (offB >= 0) {
            const float4* pB = hwc4 + offB + cg;
            Ba = pB[0];
            Bc = pB[32];
            Bb = pB[WS * 32];
            Bd = pB[WS * 32 + 32];
        }

        float4 vA = Z, vB = Z;
        if (offA >= 0) {
            const float4 w = sWt[jA];
            vA.x = Aa.x * w.x + Ab.x * w.y + Ac.x * w.z + Ad.x * w.w;
            vA.y = Aa.y * w.x + Ab.y * w.y + Ac.y * w.z + Ad.y * w.w;
            vA.z = Aa.z * w.x + Ab.z * w.y + Ac.z * w.z + Ad.z * w.w;
            vA.w = Aa.w * w.x + Ab.w * w.y + Ac.w * w.z + Ad.w * w.w;
        }
        if (offB >= 0) {
            const float4 w = sWt[jB];
            vB.x = Ba.x * w.x + Bb.x * w.y + Bc.x * w.z + Bd.x * w.w;
            vB.y = Ba.y * w.x + Bb.y * w.y + Bc.y * w.z + Bd.y * w.w;
            vB.z = Ba.z * w.x + Bb.z * w.y + Bc.z * w.z + Bd.z * w.w;
            vB.w = Ba.w * w.x + Bb.w * w.y + Bc.w * w.z + Bd.w * w.w;
        }
        out4[((size_t)b * TOPK + p0 + jA) * 32 + cg] = vA;
        out4[((size_t)b * TOPK + p0 + jB) * 32 + cg] = vB;
    }
}

// ---------------------------------------------------------------------------
extern "C" void kernel_launch(void* const* d_in, const int* in_sizes, int n_in,
                              void* d_out, int out_size)
{
    const float* prob   = (const float*)d_in[0];      // [B,1,H,W]
    const float* feat   = (const float*)d_in[1];      // [B,C,HS,WS]
    const float* ratio  = (const float*)d_in[2];      // [B,1]
    const int*   rshape = (const int*)d_in[3];        // [B,2] int32 (or int64-packed)

    float* pts_out = (float*)d_out;                        // [B,TOPK,2]
    float* des_out = (float*)d_out + (size_t)B * TOPK * 2; // [B,TOPK,C]

    select_kernel<<<B, 1024>>>(prob, ratio, rshape, pts_out);
    transpose_kernel<<<TBLOCKS, dim3(32, 8)>>>(feat);
    gather_kernel<<<dim3(TOPK / 80, B), 256>>>(des_out);
}